// round 15
// baseline (speedup 1.0000x reference)
#include <cuda_runtime.h>
#include <math.h>

// ---------------- problem constants ----------------
#define NB    32
#define NCOL  160
#define NOUT  10
#define OFF_DIST 320
#define OFF_PROB 5440
#define OFF_LOSS 10560

#define NT    512
#define BPB   9                   // blocks per batch
#define NBLK  (NB*BPB)            // 288
#define NWT   235                 // warp-tickets per batch (235*32 = 7520 items exactly)

// smem layout (words)
#define SXSTR 524                 // 524/4=131 odd -> conflict-free; holds up to idx 519
#define SXW   (8*SXSTR)           // 4192
// w regions: set3(L256,WW260) set2(154,156) set1(103,108) set0(52,60)
#define SW3   0
#define SW2   10400
#define SW1   16640
#define SW0   20960
#define SWTOT 23360
#define SRED  (SXW + SWTOT)       // 27552
#define SM_WORDS (SRED + 320)     // 27872
#define SM_BYTES (SM_WORDS*4)     // 111488 B -> 2 blocks/SM at 512 threads

// item space per batch (expensive-first): set3 [0,1320) set2 [1320,3120) set1 [3120,5200) set0 [5200,7520)
#define I3 1320
#define I2 3120
#define I1 5200

__device__ unsigned g_d[NB*NCOL] = {};
__device__ unsigned g_q[NB*NCOL] = {};
__device__ unsigned g_wt[NB] = {};
__device__ unsigned g_ctr = 0;

__device__ __forceinline__ unsigned fenc(float f){unsigned u=__float_as_uint(f);return (u&0x80000000u)?~u:(u|0x80000000u);}
__device__ __forceinline__ float fdec(unsigned e){unsigned u=(e&0x80000000u)?(e&0x7fffffffu):~e;return __uint_as_float(u);}
__device__ __forceinline__ unsigned ienc(float f){ return ~fenc(f); }   // max(ienc)=min(f); 0 sentinel
__device__ __forceinline__ float idec(unsigned e){ return fdec(~e); }

// 8-ring rotations (compile-time renaming)
#define Q0 y0,y1,y2,y3,y4,y5,y6,y7
#define Q1 y1,y2,y3,y4,y5,y6,y7,y0
#define Q2 y2,y3,y4,y5,y6,y7,y0,y1
#define Q3 y3,y4,y5,y6,y7,y0,y1,y2
#define Q4 y4,y5,y6,y7,y0,y1,y2,y3
#define Q5 y5,y6,y7,y0,y1,y2,y3,y4
#define Q6 y6,y7,y0,y1,y2,y3,y4,y5
#define Q7 y7,y0,y1,y2,y3,y4,y5,y6

#define S8_(W,JJ,a0,a1,a2,a3,a4,a5,a6,a7) do { \
    float w_ = (W); \
    acc0 += fabsf(a0 - w_);  acc1 += fabsf(a1 - w_); \
    acc2 += fabsf(a2 - w_);  acc3 += fabsf(a3 - w_); \
    acc4 += fabsf(a4 - w_);  acc5 += fabsf(a5 - w_); \
    acc6 += fabsf(a6 - w_);  acc7 += fabsf(a7 - w_); \
    a0 = xr[(JJ) + 8]; \
} while (0)
#define S8(W, JJ, RING) S8_(W, JJ, RING)

#define FIN(K, A) do { \
    int mm = 8*tl + (K); \
    if (mm < M) { \
        float d_ = (A) * INVL * __ldg(&pr[mm]); \
        dmin = fminf(dmin, d_); \
        qmin = fminf(qmin, fabsf(d_)); \
    } \
} while (0)

// ---------------- one item = 8 consecutive windows ----------------
template<int L, int M, int WW, int SBASE>
__device__ __forceinline__ void item1(const float* __restrict__ sx, const float* __restrict__ swr,
                                      const float* __restrict__ pcm,
                                      unsigned* __restrict__ sden, unsigned* __restrict__ sq, int local)
{
    constexpr int MAIN = L & ~7;
    constexpr int REM  = L & 7;
    constexpr float INVL = 1.0f/(float)L;

    int tl = local / 40;
    int nc = local - tl*40;
    int c  = nc & 7;
    const float* xr = sx + c*SXSTR + 8*tl;
    const float* wr = swr + nc*WW;

    float4 xa = *(const float4*)(xr);
    float4 xb = *(const float4*)(xr + 4);
    float y0=xa.x,y1=xa.y,y2=xa.z,y3=xa.w, y4=xb.x,y5=xb.y,y6=xb.z,y7=xb.w;
    float acc0=0.f,acc1=0.f,acc2=0.f,acc3=0.f,acc4=0.f,acc5=0.f,acc6=0.f,acc7=0.f;

    float4 wA = *(const float4*)(wr);
    for (int j = 0; j < MAIN; j += 8) {
        float4 wB = *(const float4*)(wr + j + 4);
        S8(wA.x, j+0, Q0); S8(wA.y, j+1, Q1); S8(wA.z, j+2, Q2); S8(wA.w, j+3, Q3);
        wA = *(const float4*)(wr + j + 8);     // in-row pad guaranteed by WW
        S8(wB.x, j+4, Q4); S8(wB.y, j+5, Q5); S8(wB.z, j+6, Q6); S8(wB.w, j+7, Q7);
    }
    if (REM > 0) {                              // wA holds wr[MAIN..MAIN+3]
        S8(wA.x, MAIN+0, Q0);
        if (REM > 1) S8(wA.y, MAIN+1, Q1);
        if (REM > 2) S8(wA.z, MAIN+2, Q2);
        if (REM > 3) S8(wA.w, MAIN+3, Q3);
    }
    if (REM > 4) {
        float4 v = *(const float4*)(wr + MAIN + 4);
        S8(v.x, MAIN+4, Q4);
        if (REM > 5) S8(v.y, MAIN+5, Q5);
        if (REM > 6) S8(v.z, MAIN+6, Q6);
    }

    const float* pr = pcm + c*M;
    float dmin = 3.4e38f, qmin = 3.4e38f;
    FIN(0,acc0); FIN(1,acc1); FIN(2,acc2); FIN(3,acc3);
    FIN(4,acc4); FIN(5,acc5); FIN(6,acc6); FIN(7,acc7);

    atomicMax(&sden[SBASE + nc], ienc(dmin));
    atomicMax(&sq[SBASE + nc],   ienc(qmin));
}

template<int L, int WW>
__device__ __forceinline__ void stage_w(float* __restrict__ dst, const float* __restrict__ wp, int tid) {
    for (int i2 = tid; i2 < 40*L; i2 += NT) {
        int r = i2 / L, j = i2 - r*L;
        dst[r*WW + j] = wp[i2];
    }
}

// ---------------- fused persistent kernel ----------------
__global__ __launch_bounds__(NT, 2)
void k_all(const float* __restrict__ x,
           const float* __restrict__ w0, const float* __restrict__ w1,
           const float* __restrict__ w2, const float* __restrict__ w3,
           const float* __restrict__ p0, const float* __restrict__ p1,
           const float* __restrict__ p2, const float* __restrict__ p3,
           const float* __restrict__ Wout, float* __restrict__ out)
{
    extern __shared__ float sm[];
    float* sx = sm;
    float* sw = sm + SXW;
    unsigned* sden = (unsigned*)(sm + SRED);   // [160]
    unsigned* sq   = sden + 160;               // [160]
    __shared__ unsigned s_old;

    int tid = threadIdx.x;
    int bx = blockIdx.x;
    int b = bx / BPB;

    if (tid < 320) sden[tid] = 0u;             // sden + sq

    // ---- block 0: losses first (uses sm[0..2432) only; x/w staged after) ----
    if (bx == 0) {
        float* sf   = sm;            // [640]
        float* sr   = sm + 640;      // [640]
        float* sval = sm + 1280;     // [512]
        float* sreg = sm + 1792;     // [512]

        float reg = 0.f;
        for (int i = tid; i < NOUT*NCOL; i += NT) reg += fabsf(Wout[i]);
        sreg[tid] = reg;

        const int Ls[4] = {52, 103, 154, 256};
        const float* wls[4] = {w0, w1, w2, w3};
        const signed char I1a[10] = {0,0,0,0,1,1,1,2,2,3};
        const signed char J1a[10] = {1,2,3,4,2,3,4,3,4,4};

        for (int u = tid; u < 640; u += NT) {
            int pp = u >> 1, h = u & 1;
            int s = pp / 80; int r = pp - s*80;
            int c = r / 10; int pr = r - c*10;
            int i = I1a[pr], j = J1a[pr];
            int L = Ls[s];
            const float* wa = wls[s] + (i*8 + c)*L;
            const float* wb = wls[s] + (j*8 + c)*L;
            int k0 = h ? (L >> 1) : 0;
            int k1 = h ? L : (L >> 1);
            float af = 0.f, ar = 0.f;
#pragma unroll 8
            for (int k = k0; k < k1; k++) {
                float t = wa[k] - wb[k];
                float df = t + 1e-6f, dr = 1e-6f - t;
                af += df*df; ar += dr*dr;
            }
            sf[u] = af; sr[u] = ar;
        }
        __syncthreads();
        float val = 0.f;
        for (int pp = tid; pp < 320; pp += NT) {
            float ssf = sf[2*pp] + sf[2*pp + 1];
            float ssr = sr[2*pp] + sr[2*pp + 1];
            val += (expf(-sqrtf(ssf)) + expf(-sqrtf(ssr))) * (1.f/200.f);
        }
        sval[tid] = val;
        __syncthreads();
        for (int off = 256; off; off >>= 1) {
            if (tid < off) { sval[tid] += sval[tid+off]; sreg[tid] += sreg[tid+off]; }
            __syncthreads();
        }
        if (tid == 0) out[OFF_LOSS] = 0.1f*(sreg[0]/1600.f) + 0.1f*sval[0];
        __syncthreads();
    }

    // ---- stage x (warps 0-7) and all four w sets (all threads) ----
    {
        int wp_ = tid >> 5, lane = tid & 31;
        if (wp_ < 8) {
            const float* row = x + (b*8 + wp_)*512;
            float v[16]; float sv = 0.f;
#pragma unroll
            for (int i = 0; i < 16; i++) { v[i] = row[lane + 32*i]; sv += v[i]; }
#pragma unroll
            for (int o = 16; o; o >>= 1) sv += __shfl_xor_sync(0xffffffffu, sv, o);
            float mu = sv * (1.f/512.f);
            float qq = 0.f;
#pragma unroll
            for (int i = 0; i < 16; i++) { float d = v[i]-mu; qq += d*d; }
#pragma unroll
            for (int o = 16; o; o >>= 1) qq += __shfl_xor_sync(0xffffffffu, qq, o);
            float sc = 1.f / (sqrtf(qq * (1.f/511.f)) + 1e-8f);
            float* orow = sx + wp_*SXSTR;
#pragma unroll
            for (int i = 0; i < 16; i++) orow[lane + 32*i] = (v[i]-mu)*sc;
            if (lane < SXSTR - 512) orow[512 + lane] = 0.f;
        }
        stage_w<256,260>(sw + SW3, w3, tid);
        stage_w<154,156>(sw + SW2, w2, tid);
        stage_w<103,108>(sw + SW1, w1, tid);
        stage_w< 52, 60>(sw + SW0, w0, tid);
    }
    __syncthreads();

    // ---- barrier-free warp-level work stealing over this batch's items ----
    {
        int lane = tid & 31;
        for (;;) {
            unsigned wt;
            if (lane == 0) wt = atomicAdd(&g_wt[b], 1u);
            wt = __shfl_sync(0xffffffffu, wt, 0);
            if (wt >= NWT) break;
            int idx = (int)wt*32 + lane;
            if (idx < I3)      item1<256,257,260,120>(sx, sw + SW3, p3, sden, sq, idx);
            else if (idx < I2) item1<154,359,156, 80>(sx, sw + SW2, p2, sden, sq, idx - I3);
            else if (idx < I1) item1<103,410,108, 40>(sx, sw + SW1, p1, sden, sq, idx - I2);
            else               item1< 52,461, 60,  0>(sx, sw + SW0, p0, sden, sq, idx - I1);
        }
    }

    // ---- flush block partials ----
    __syncthreads();
    if (tid < NCOL) {
        unsigned dv = sden[tid], qv = sq[tid];
        int gi = b*NCOL + tid;
        if (dv) atomicMax(&g_d[gi], dv);
        if (qv) atomicMax(&g_q[gi], qv);
    }

    // ---- completion counter: last block finalizes ----
    __threadfence();
    __syncthreads();
    if (tid == 0) s_old = atomicAdd(&g_ctr, 1u);
    __syncthreads();
    if (s_old != NBLK - 1) return;

    __threadfence();
    float* sprob = sm;              // [5120]
    float* swout = sm + 5120;       // [1600]
    for (int i = tid; i < NB*NCOL; i += NT) {
        unsigned de = atomicMax(&g_d[i], 0u);   // L2-coherent read
        unsigned qe = atomicMax(&g_q[i], 0u);
        g_d[i] = 0u; g_q[i] = 0u;               // reset for next replay
        float qv = idec(qe);
        float p = expf(-qv*qv);
        out[OFF_DIST + i] = idec(de);
        out[OFF_PROB + i] = p;
        sprob[i] = p;
    }
    for (int i = tid; i < NOUT*NCOL; i += NT) swout[i] = Wout[i];
    __syncthreads();
    for (int tt = tid; tt < NB*NOUT; tt += NT) {
        int bb = tt / NOUT, o = tt - bb*NOUT;
        const float* pr = sprob + bb*NCOL;
        const float* wr = swout + o*NCOL;
        float acc = 0.f;
#pragma unroll 8
        for (int j = 0; j < NCOL; j++) acc += pr[j]*wr[j];
        out[bb*NOUT + o] = acc;
    }
    if (tid < NB) g_wt[tid] = 0u;               // reset counters for replay
    if (tid == 0) g_ctr = 0u;
}

// ---------------- launch ----------------
extern "C" void kernel_launch(void* const* d_in, const int* in_sizes, int n_in,
                              void* d_out, int out_size) {
    const float* x = nullptr;
    const float* w[4] = {nullptr,nullptr,nullptr,nullptr};
    const float* pcm[4] = {nullptr,nullptr,nullptr,nullptr};
    const float* Wout = nullptr;
    for (int i = 0; i < n_in; i++) {
        switch (in_sizes[i]) {
            case 131072: x = (const float*)d_in[i]; break;
            case 2080:  w[0] = (const float*)d_in[i]; break;
            case 4120:  w[1] = (const float*)d_in[i]; break;
            case 6160:  w[2] = (const float*)d_in[i]; break;
            case 10240: w[3] = (const float*)d_in[i]; break;
            case 3688:  pcm[0] = (const float*)d_in[i]; break;
            case 3280:  pcm[1] = (const float*)d_in[i]; break;
            case 2872:  pcm[2] = (const float*)d_in[i]; break;
            case 2056:  pcm[3] = (const float*)d_in[i]; break;
            case 1600:  Wout = (const float*)d_in[i]; break;
            default: break;
        }
    }
    float* out = (float*)d_out;

    cudaFuncSetAttribute(k_all, cudaFuncAttributeMaxDynamicSharedMemorySize, SM_BYTES);

    k_all<<<NBLK, NT, SM_BYTES>>>(x, w[0], w[1], w[2], w[3],
                                  pcm[0], pcm[1], pcm[2], pcm[3], Wout, out);
    (void)out_size;
}